// round 4
// baseline (speedup 1.0000x reference)
#include <cuda_runtime.h>
#include <math.h>

#define TMAX 64

// ANCHORS/stride per layer (exact: divisors are powers of two, bit-identical to fdiv)
__constant__ float c_allg[3][18] = {
  {0.3125f,0.40625f, 0.5f,0.9375f, 1.03125f,0.71875f, 0.9375f,1.90625f, 1.9375f,1.40625f,
   1.84375f,3.71875f, 3.625f,2.8125f, 4.875f,6.1875f, 11.65625f,10.1875f},
  {0.625f,0.8125f, 1.0f,1.875f, 2.0625f,1.4375f, 1.875f,3.8125f, 3.875f,2.8125f,
   3.6875f,7.4375f, 7.25f,5.625f, 9.75f,12.375f, 23.3125f,20.375f},
  {1.25f,1.625f, 2.0f,3.75f, 4.125f,2.875f, 3.75f,7.625f, 7.75f,5.625f,
   7.375f,14.875f, 14.5f,11.25f, 19.5f,24.75f, 46.625f,40.75f}
};

// scratch (no allocations allowed)
__device__ float4 g_box[3*16*TMAX];
__device__ float2 g_meta[3*16*TMAX];
__device__ float4 g_ext4[3*16*TMAX];
__device__ float2 g_ext2[3*16*TMAX];
__device__ int    g_cnt[3*16];
__device__ double   g_acc   = 0.0;
__device__ unsigned g_count = 0u;

__device__ __forceinline__ float slog(float x) { return x > 0.f ? __logf(x) : -100.f; }
__device__ __forceinline__ float sigm(float x) { return 1.f/(1.f + __expf(-x)); }

// Target preprocessing: grid (B,3), 64 threads. One thread per target;
// ballot prefix-sum compacts valid targets preserving order (last-wins scatter).
__global__ void k_tgt(const float* __restrict__ tg, int T,
                      int fs0, int fs1, int fs2)
{
    int b     = blockIdx.x;
    int layer = blockIdx.y;
    int tid   = threadIdx.x;
    if (b == 0 && layer == 0 && tid == 0) g_acc = 0.0;

    int fs = (layer == 0) ? fs0 : ((layer == 1) ? fs1 : fs2);
    int group = 2 - layer;
    float fsf = (float)fs;

    bool valid = false;
    float cf = 0.f, tx = 0.f, ty = 0.f, tw = 0.f, th = 0.f;
    if (tid < T) {
        const float* L = tg + ((size_t)b*T + tid)*5;
        cf = L[0];
        float x = L[1], y = L[2], w = L[3], h = L[4];
        valid = (cf + x + y + w + h) > 0.f;
        tx = x*fsf; ty = y*fsf; tw = w*fsf; th = h*fsf;
    }

    __shared__ int s_w0;
    int lane = tid & 31, wi = tid >> 5;
    unsigned ball = __ballot_sync(0xffffffffu, valid);
    int pre = __popc(ball & ((1u << lane) - 1u));
    if (wi == 0 && lane == 0) s_w0 = __popc(ball);
    __syncthreads();
    if (wi == 1) pre += s_w0;
    if (tid == 63) g_cnt[layer*16 + b] = s_w0 + __popc(ball);

    if (!valid) return;

    float twth = tw*th;
    // argmax over 9 anchor IoUs (first max wins)
    float best = -1.f; int bi = 0;
    #pragma unroll
    for (int i = 0; i < 9; ++i) {
        float aw = c_allg[layer][2*i], ah = c_allg[layer][2*i+1];
        float mw = fminf(tw, aw), mh = fminf(th, ah);
        float inter = (mw > 0.f && mh > 0.f) ? mw*mh : 0.f;
        float iou = inter / (twth + aw*ah - inter);
        if (iou > best) { best = iou; bi = i; }
    }
    int bn = bi - (bi/3)*3;
    bool sel = (bi/3) == group;

    int idx = (layer*16 + b)*TMAX + pre;
    g_box[idx] = make_float4(tx - 0.5f*tw, ty - 0.5f*th, tx + 0.5f*tw, ty + 0.5f*th);
    int key = -1;
    if (sel) {
        int gi = (int)tx, gj = (int)ty;
        if (gi >= 0 && gi < fs && gj >= 0 && gj < fs) {   // mode='drop'
            key = (bn << 28) | (gj << 14) | gi;
            float aw = c_allg[layer][2*(3*group + bn)];
            float ah = c_allg[layer][2*(3*group + bn) + 1];
            g_ext4[idx] = make_float4(tx - (float)gi, ty - (float)gj,
                                      logf(tw/aw + 1e-16f), logf(th/ah + 1e-16f));
            g_ext2[idx] = make_float2(sqrtf(2.f - twth/(fsf*fsf)),
                                      __int_as_float((int)cf));
        }
    }
    g_meta[idx] = make_float2(0.7f*twth, __int_as_float(key));
}

// Per-cell loss, 4 cells per thread (1024 cells per 256-thread block).
// blockIdx.x partitions tiles across layers; blockIdx.y = batch.
__global__ __launch_bounds__(256)
void k_loss(const float* __restrict__ r0, const float* __restrict__ r1,
            const float* __restrict__ r2,
            int HW0, int W0, int HW1, int W1, int HW2, int W2,
            int nb0, int nb01, float* __restrict__ out)
{
    __shared__ float4 sbox[TMAX];
    __shared__ float2 smeta[TMAX];
    __shared__ float4 sext4[TMAX];
    __shared__ float2 sext2[TMAX];
    __shared__ int scnt;
    __shared__ float swsum[8];

    int bx = blockIdx.x;
    int layer; const float* raw; int HW, W, base;
    if (bx < nb0)       { layer = 0; raw = r0; HW = HW0; W = W0; base = 0;    }
    else if (bx < nb01) { layer = 1; raw = r1; HW = HW1; W = W1; base = nb0;  }
    else                { layer = 2; raw = r2; HW = HW2; W = W2; base = nb01; }

    int b   = blockIdx.y;
    int tid = threadIdx.x;
    int lb  = layer*16 + b;

    // cooperative smem fill: 4 ranges of 64 threads, one element each
    {
        int r = tid >> 6, i = tid & 63;
        int gidx = lb*TMAX + i;
        if      (r == 0) sbox[i]  = g_box[gidx];
        else if (r == 1) smeta[i] = g_meta[gidx];
        else if (r == 2) sext4[i] = g_ext4[gidx];
        else             sext2[i] = g_ext2[gidx];
        if (tid == 0) scnt = g_cnt[lb];
    }
    __syncthreads();

    int tile = (bx - base)*1024 + tid;
    int nc3  = 3*HW;
    float invHW = 1.f/(float)HW;
    float invW  = 1.f/(float)W;

    // per-cell persistent state
    float atlx[4], atly[4], abrx[4], abry[4], ca[4], o4v[4];
    int   ckey[4], tmi[4], anyv[4];

    #pragma unroll
    for (int i = 0; i < 4; ++i) {
        int cell = tile + i*256;
        tmi[i] = -1; anyv[i] = 0;
        if (cell < nc3) {
            int a  = (int)((float)cell * invHW);
            int hw = cell - a*HW;
            if (hw < 0)        { a--; hw += HW; }
            else if (hw >= HW) { a++; hw -= HW; }
            int h  = (int)((float)hw * invW);
            int w  = hw - h*W;
            if (w < 0)       { h--; w += W; }
            else if (w >= W) { h++; w -= W; }
            const float* p = raw + ((size_t)b*255 + (size_t)a*85)*(size_t)HW + hw;
            float o0 = __ldg(p);
            float o1 = __ldg(p + HW);
            float o2 = __ldg(p + 2*HW);
            float o3 = __ldg(p + 3*HW);
            o4v[i]   = __ldg(p + 4*HW);
            float maw = c_allg[layer][2*(3*(2-layer) + a)];
            float mah = c_allg[layer][2*(3*(2-layer) + a) + 1];
            float pw = __expf(o2)*maw, ph = __expf(o3)*mah;
            float px = sigm(o0) + (float)w, py = sigm(o1) + (float)h;
            atlx[i] = px - 0.5f*pw;  atly[i] = py - 0.5f*ph;
            abrx[i] = px + 0.5f*pw;  abry[i] = py + 0.5f*ph;
            ca[i]   = 0.7f*(pw*ph);
            ckey[i] = (a << 28) | (h << 14) | w;
        } else {
            atlx[i] =  1e30f; atly[i] =  1e30f;
            abrx[i] = -1e30f; abry[i] = -1e30f;
            ca[i] = 0.f; o4v[i] = 0.f; ckey[i] = -2;
        }
    }

    int cnt = scnt;
    for (int t = 0; t < cnt; ++t) {
        float4 bb = sbox[t];
        float2 mm = smeta[t];
        int mkey = __float_as_int(mm.y);
        #pragma unroll
        for (int i = 0; i < 4; ++i) {
            float ix = fminf(abrx[i], bb.z) - fmaxf(atlx[i], bb.x);
            float iy = fminf(abry[i], bb.w) - fmaxf(atly[i], bb.y);
            float ii = fminf(ix, iy);
            float lhs = fmaf(1.7f, ix*iy, -ca[i]);
            // piou > 0.7  <=>  ix>0 & iy>0 & 1.7*ai - 0.7*areaA > 0.7*areaB
            anyv[i] |= (ii > 0.f) & (lhs > mm.x);
            if (mkey == ckey[i]) tmi[i] = t;   // last match wins
        }
    }

    float lsum = 0.f;
    #pragma unroll
    for (int i = 0; i < 4; ++i) {
        int cell = tile + i*256;
        if (cell >= nc3) continue;
        if (tmi[i] >= 0) {
            // reload channel data for the rare assigned-cell path
            int a  = ckey[i] >> 28;
            int hw = cell - a*HW;
            const float* p = raw + ((size_t)b*255 + (size_t)a*85)*(size_t)HW + hw;
            float o0 = __ldg(p);
            float o1 = __ldg(p + HW);
            float o2 = __ldg(p + 2*HW);
            float o3 = __ldg(p + 3*HW);
            float s0 = sigm(o0), s1 = sigm(o1), s4 = sigm(o4v[i]);
            float4 e4 = sext4[tmi[i]];
            float2 e2 = sext2[tmi[i]];
            float ts2 = e2.x*e2.x;
            int cls = __float_as_int(e2.y);
            lsum -= ts2*( e4.x*slog(s0) + (1.f - e4.x)*slog(1.f - s0)
                        + e4.y*slog(s1) + (1.f - e4.y)*slog(1.f - s1) );
            float dw = o2 - e4.z, dh = o3 - e4.w;
            lsum += 0.5f*ts2*(dw*dw + dh*dh);
            lsum -= slog(s4);
            for (int c = 0; c < 80; ++c) {
                float scc = sigm(__ldg(p + (size_t)(5 + c)*HW));
                lsum -= (c == cls) ? slog(scc) : slog(1.f - scc);
            }
        } else if (!anyv[i]) {
            float s4 = sigm(o4v[i]);
            lsum -= slog(1.f - s4);
        }
        // (anyv && tmi<0) -> obj_mask = 0 -> no contribution
    }

    // block reduction + one atomic per block; last block writes the output
    #pragma unroll
    for (int off = 16; off; off >>= 1)
        lsum += __shfl_xor_sync(0xffffffffu, lsum, off);
    if ((tid & 31) == 0) swsum[tid >> 5] = lsum;
    __syncthreads();
    if (tid == 0) {
        double bsum = 0.0;
        #pragma unroll
        for (int i = 0; i < 8; ++i) bsum += (double)swsum[i];
        atomicAdd(&g_acc, bsum);
        __threadfence();
        unsigned total = gridDim.x * gridDim.y;
        unsigned prev = atomicAdd(&g_count, 1u);
        if (prev == total - 1u) {
            out[0] = (float)g_acc;
            g_acc = 0.0;
            g_count = 0u;
        }
    }
}

extern "C" void kernel_launch(void* const* d_in, const int* in_sizes, int n_in,
                              void* d_out, int out_size)
{
    const float* r0 = (const float*)d_in[0];
    const float* r1 = (const float*)d_in[1];
    const float* r2 = (const float*)d_in[2];
    const float* targets = (const float*)d_in[3];
    const int B = 16;
    int T = in_sizes[3] / (B*5);
    if (T > TMAX) T = TMAX;

    int HW0 = in_sizes[0] / (B*255);
    int HW1 = in_sizes[1] / (B*255);
    int HW2 = in_sizes[2] / (B*255);
    int W0 = (int)(sqrt((double)HW0) + 0.5);
    int W1 = (int)(sqrt((double)HW1) + 0.5);
    int W2 = (int)(sqrt((double)HW2) + 0.5);

    dim3 tgrid(B, 3);
    k_tgt<<<tgrid, 64>>>(targets, T, W0, W1, W2);

    int nb0 = (3*HW0 + 1023)/1024;
    int nb1 = (3*HW1 + 1023)/1024;
    int nb2 = (3*HW2 + 1023)/1024;
    dim3 lgrid(nb0 + nb1 + nb2, B);
    k_loss<<<lgrid, 256>>>(r0, r1, r2,
                           HW0, W0, HW1, W1, HW2, W2,
                           nb0, nb0 + nb1, (float*)d_out);
}

// round 5
// speedup vs baseline: 2.0575x; 2.0575x over previous
#include <cuda_runtime.h>
#include <math.h>

#define TMAX 64
#define TPAD 68   // TMAX + 4 pad slots for the x4-unrolled loop

// ANCHORS/stride per layer (exact: divisors are powers of two, bit-identical to fdiv)
__constant__ float c_allg[3][18] = {
  {0.3125f,0.40625f, 0.5f,0.9375f, 1.03125f,0.71875f, 0.9375f,1.90625f, 1.9375f,1.40625f,
   1.84375f,3.71875f, 3.625f,2.8125f, 4.875f,6.1875f, 11.65625f,10.1875f},
  {0.625f,0.8125f, 1.0f,1.875f, 2.0625f,1.4375f, 1.875f,3.8125f, 3.875f,2.8125f,
   3.6875f,7.4375f, 7.25f,5.625f, 9.75f,12.375f, 23.3125f,20.375f},
  {1.25f,1.625f, 2.0f,3.75f, 4.125f,2.875f, 3.75f,7.625f, 7.75f,5.625f,
   7.375f,14.875f, 14.5f,11.25f, 19.5f,24.75f, 46.625f,40.75f}
};

// scratch (no allocations allowed)
__device__ float4 g_box[3*16*TPAD];
__device__ float2 g_meta[3*16*TPAD];
__device__ float4 g_ext4[3*16*TMAX];
__device__ float2 g_ext2[3*16*TMAX];
__device__ int    g_cnt[3*16];
__device__ double   g_acc   = 0.0;
__device__ unsigned g_count = 0u;

__device__ __forceinline__ float slog(float x) { return x > 0.f ? __logf(x) : -100.f; }
__device__ __forceinline__ float sigm(float x) { return 1.f/(1.f + __expf(-x)); }

// Target preprocessing: grid (B,3), 64 threads. One thread per target;
// ballot prefix-sum compacts valid targets in order (preserves last-wins scatter).
// Also writes 4 inert pad entries so the loss loop can unroll by 4.
__global__ void k_tgt(const float* __restrict__ tg, int T,
                      int fs0, int fs1, int fs2)
{
    int b     = blockIdx.x;
    int layer = blockIdx.y;
    int tid   = threadIdx.x;
    if (b == 0 && layer == 0 && tid == 0) g_acc = 0.0;

    int fs = (layer == 0) ? fs0 : ((layer == 1) ? fs1 : fs2);
    int group = 2 - layer;
    float fsf = (float)fs;
    int base = (layer*16 + b);

    bool valid = false;
    float cf = 0.f, tx = 0.f, ty = 0.f, tw = 0.f, th = 0.f;
    if (tid < T) {
        const float* L = tg + ((size_t)b*T + tid)*5;
        cf = L[0];
        float x = L[1], y = L[2], w = L[3], h = L[4];
        valid = (cf + x + y + w + h) > 0.f;
        tx = x*fsf; ty = y*fsf; tw = w*fsf; th = h*fsf;
    }

    __shared__ int s_w0, s_total;
    int lane = tid & 31, wi = tid >> 5;
    unsigned ball = __ballot_sync(0xffffffffu, valid);
    int pre = __popc(ball & ((1u << lane) - 1u));
    if (wi == 0 && lane == 0) s_w0 = __popc(ball);
    __syncthreads();
    if (wi == 1) pre += s_w0;
    if (tid == 32) s_total = s_w0 + __popc(ball);
    __syncthreads();
    int total = s_total;
    if (tid == 0) g_cnt[base] = total;

    // 4 inert pad entries: never intersect, never match any cell key
    if (tid < 4) {
        int idx = base*TPAD + total + tid;
        g_box[idx]  = make_float4(2e9f, 2e9f, -2e9f, -2e9f);
        g_meta[idx] = make_float2(0.f, __int_as_float(-1));
    }

    if (!valid) return;

    float twth = tw*th;
    // argmax over 9 anchor IoUs (first max wins)
    float best = -1.f; int bi = 0;
    #pragma unroll
    for (int i = 0; i < 9; ++i) {
        float aw = c_allg[layer][2*i], ah = c_allg[layer][2*i+1];
        float mw = fminf(tw, aw), mh = fminf(th, ah);
        float inter = (mw > 0.f && mh > 0.f) ? mw*mh : 0.f;
        float iou = inter / (twth + aw*ah - inter);
        if (iou > best) { best = iou; bi = i; }
    }
    int bn = bi - (bi/3)*3;
    bool sel = (bi/3) == group;

    g_box[base*TPAD + pre] = make_float4(tx - 0.5f*tw, ty - 0.5f*th,
                                         tx + 0.5f*tw, ty + 0.5f*th);
    int key = -1;
    if (sel) {
        int gi = (int)tx, gj = (int)ty;
        if (gi >= 0 && gi < fs && gj >= 0 && gj < fs) {   // mode='drop'
            key = (bn << 28) | (gj << 14) | gi;
            float aw = c_allg[layer][2*(3*group + bn)];
            float ah = c_allg[layer][2*(3*group + bn) + 1];
            g_ext4[base*TMAX + pre] = make_float4(tx - (float)gi, ty - (float)gj,
                                      logf(tw/aw + 1e-16f), logf(th/ah + 1e-16f));
            g_ext2[base*TMAX + pre] = make_float2(sqrtf(2.f - twth/(fsf*fsf)),
                                      __int_as_float((int)cf));
        }
    }
    g_meta[base*TPAD + pre] = make_float2(0.7f*twth, __int_as_float(key));
}

// Per-cell loss, 1 cell/thread, target loop unrolled x4 for MLP.
__global__ __launch_bounds__(256)
void k_loss(const float* __restrict__ r0, const float* __restrict__ r1,
            const float* __restrict__ r2,
            int HW0, int W0, int HW1, int W1, int HW2, int W2,
            int nb0, int nb01, float* __restrict__ out)
{
    __shared__ float4 sbox[TPAD];
    __shared__ float2 smeta[TPAD];
    __shared__ float4 sext4[TMAX];
    __shared__ float2 sext2[TMAX];
    __shared__ int scnt;
    __shared__ float swsum[8];

    int bx = blockIdx.x;
    int layer; const float* raw; int HW, W, base;
    if (bx < nb0)       { layer = 0; raw = r0; HW = HW0; W = W0; base = 0;    }
    else if (bx < nb01) { layer = 1; raw = r1; HW = HW1; W = W1; base = nb0;  }
    else                { layer = 2; raw = r2; HW = HW2; W = W2; base = nb01; }

    int b   = blockIdx.y;
    int tid = threadIdx.x;
    int lb  = layer*16 + b;

    // cooperative smem fill
    {
        int r = tid >> 7, i = tid & 127;
        if (r == 0) {
            if (i < TPAD) { sbox[i] = g_box[lb*TPAD + i]; smeta[i] = g_meta[lb*TPAD + i]; }
        } else {
            if (i < TMAX) { sext4[i] = g_ext4[lb*TMAX + i]; sext2[i] = g_ext2[lb*TMAX + i]; }
        }
        if (tid == 0) scnt = g_cnt[lb];
    }
    __syncthreads();

    int cell = (bx - base)*256 + tid;
    float lsum = 0.f;
    if (cell < 3*HW) {
        int a  = cell / HW;
        int hw = cell - a*HW;
        int h  = hw / W;
        int w  = hw - h*W;
        const float* p = raw + ((size_t)b*255 + (size_t)a*85)*(size_t)HW + hw;
        float o0 = __ldg(p);
        float o1 = __ldg(p + HW);
        float o2 = __ldg(p + 2*HW);
        float o3 = __ldg(p + 3*HW);
        float o4 = __ldg(p + 4*HW);
        float s0 = sigm(o0), s1 = sigm(o1), s4 = sigm(o4);
        float maw = c_allg[layer][2*(3*(2-layer) + a)];
        float mah = c_allg[layer][2*(3*(2-layer) + a) + 1];
        float pw = __expf(o2)*maw, ph = __expf(o3)*mah;
        float px = s0 + (float)w, py = s1 + (float)h;
        float atlx = px - 0.5f*pw, atly = py - 0.5f*ph;
        float abrx = px + 0.5f*pw, abry = py + 0.5f*ph;
        float ca = 0.7f*(pw*ph);
        int ckey = (a << 28) | (h << 14) | w;

        int any = 0;
        int tmi = -1;
        int cnt4 = (scnt + 3) & ~3;
        for (int t = 0; t < cnt4; t += 4) {
            float4 b0 = sbox[t],   b1 = sbox[t+1], b2 = sbox[t+2], b3 = sbox[t+3];
            float2 m0 = smeta[t],  m1 = smeta[t+1], m2 = smeta[t+2], m3 = smeta[t+3];
            // piou > 0.7  <=>  ix>0 & iy>0 & 1.7*ai - 0.7*areaA > 0.7*areaB
            {
                float ix = fminf(abrx, b0.z) - fmaxf(atlx, b0.x);
                float iy = fminf(abry, b0.w) - fmaxf(atly, b0.y);
                any |= (fminf(ix, iy) > 0.f) & (fmaf(1.7f, ix*iy, -ca) > m0.x);
                tmi = (__float_as_int(m0.y) == ckey) ? (t)   : tmi;
            }
            {
                float ix = fminf(abrx, b1.z) - fmaxf(atlx, b1.x);
                float iy = fminf(abry, b1.w) - fmaxf(atly, b1.y);
                any |= (fminf(ix, iy) > 0.f) & (fmaf(1.7f, ix*iy, -ca) > m1.x);
                tmi = (__float_as_int(m1.y) == ckey) ? (t+1) : tmi;
            }
            {
                float ix = fminf(abrx, b2.z) - fmaxf(atlx, b2.x);
                float iy = fminf(abry, b2.w) - fmaxf(atly, b2.y);
                any |= (fminf(ix, iy) > 0.f) & (fmaf(1.7f, ix*iy, -ca) > m2.x);
                tmi = (__float_as_int(m2.y) == ckey) ? (t+2) : tmi;
            }
            {
                float ix = fminf(abrx, b3.z) - fmaxf(atlx, b3.x);
                float iy = fminf(abry, b3.w) - fmaxf(atly, b3.y);
                any |= (fminf(ix, iy) > 0.f) & (fmaf(1.7f, ix*iy, -ca) > m3.x);
                tmi = (__float_as_int(m3.y) == ckey) ? (t+3) : tmi;
            }
        }

        if (tmi >= 0) {
            float4 e4 = sext4[tmi];
            float2 e2 = sext2[tmi];
            float ts2 = e2.x*e2.x;
            int cls = __float_as_int(e2.y);
            // BCE(xy) weighted by scale^2
            lsum -= ts2*( e4.x*slog(s0) + (1.f - e4.x)*slog(1.f - s0)
                        + e4.y*slog(s1) + (1.f - e4.y)*slog(1.f - s1) );
            // 0.5 * scale^2 * (wh diff)^2
            float dw = o2 - e4.z, dh = o3 - e4.w;
            lsum += 0.5f*ts2*(dw*dw + dh*dh);
            // obj BCE, target 1
            lsum -= slog(s4);
            // class BCE over 80 channels (rare path)
            for (int c = 0; c < 80; ++c) {
                float scc = sigm(__ldg(p + (size_t)(5 + c)*HW));
                lsum -= (c == cls) ? slog(scc) : slog(1.f - scc);
            }
        } else if (!any) {
            // obj BCE, target 0 where obj_mask = 1
            lsum -= slog(1.f - s4);
        }
        // (any && tmi<0) -> obj_mask = 0 -> zero contribution
    }

    // block reduction + one atomic per block; globally-last block writes output
    #pragma unroll
    for (int off = 16; off; off >>= 1)
        lsum += __shfl_xor_sync(0xffffffffu, lsum, off);
    if ((tid & 31) == 0) swsum[tid >> 5] = lsum;
    __syncthreads();
    if (tid == 0) {
        double bsum = 0.0;
        #pragma unroll
        for (int i = 0; i < 8; ++i) bsum += (double)swsum[i];
        atomicAdd(&g_acc, bsum);
        __threadfence();
        unsigned total = gridDim.x * gridDim.y;
        unsigned prev = atomicAdd(&g_count, 1u);
        if (prev == total - 1u) {
            out[0] = (float)g_acc;
            g_acc = 0.0;       // reset for next graph replay
            g_count = 0u;
        }
    }
}

extern "C" void kernel_launch(void* const* d_in, const int* in_sizes, int n_in,
                              void* d_out, int out_size)
{
    const float* r0 = (const float*)d_in[0];
    const float* r1 = (const float*)d_in[1];
    const float* r2 = (const float*)d_in[2];
    const float* targets = (const float*)d_in[3];
    const int B = 16;
    int T = in_sizes[3] / (B*5);
    if (T > TMAX) T = TMAX;

    int HW0 = in_sizes[0] / (B*255);
    int HW1 = in_sizes[1] / (B*255);
    int HW2 = in_sizes[2] / (B*255);
    int W0 = (int)(sqrt((double)HW0) + 0.5);
    int W1 = (int)(sqrt((double)HW1) + 0.5);
    int W2 = (int)(sqrt((double)HW2) + 0.5);

    dim3 tgrid(B, 3);
    k_tgt<<<tgrid, 64>>>(targets, T, W0, W1, W2);

    int nb0 = (3*HW0 + 255)/256;
    int nb1 = (3*HW1 + 255)/256;
    int nb2 = (3*HW2 + 255)/256;
    dim3 lgrid(nb0 + nb1 + nb2, B);
    k_loss<<<lgrid, 256>>>(r0, r1, r2,
                           HW0, W0, HW1, W1, HW2, W2,
                           nb0, nb0 + nb1, (float*)d_out);
}

// round 6
// speedup vs baseline: 2.2575x; 1.0972x over previous
#include <cuda_runtime.h>
#include <math.h>

#define TMAX 64
#define TPAD 68   // TMAX + 4 pad slots for the x4-unrolled loop

// ANCHORS/stride per layer (exact: divisors are powers of two, bit-identical to fdiv)
__constant__ float c_allg[3][18] = {
  {0.3125f,0.40625f, 0.5f,0.9375f, 1.03125f,0.71875f, 0.9375f,1.90625f, 1.9375f,1.40625f,
   1.84375f,3.71875f, 3.625f,2.8125f, 4.875f,6.1875f, 11.65625f,10.1875f},
  {0.625f,0.8125f, 1.0f,1.875f, 2.0625f,1.4375f, 1.875f,3.8125f, 3.875f,2.8125f,
   3.6875f,7.4375f, 7.25f,5.625f, 9.75f,12.375f, 23.3125f,20.375f},
  {1.25f,1.625f, 2.0f,3.75f, 4.125f,2.875f, 3.75f,7.625f, 7.75f,5.625f,
   7.375f,14.875f, 14.5f,11.25f, 19.5f,24.75f, 46.625f,40.75f}
};

// scratch (no allocations allowed)
__device__ float4 g_box[3*16*TPAD];
__device__ float2 g_meta[3*16*TPAD];
__device__ float4 g_ext4[3*16*TMAX];
__device__ float2 g_ext2[3*16*TMAX];
__device__ int    g_cnt[3*16];
__device__ double   g_acc   = 0.0;
__device__ unsigned g_count = 0u;

__device__ __forceinline__ float slog(float x) { return x > 0.f ? __logf(x) : -100.f; }
__device__ __forceinline__ float sigm(float x) { return 1.f/(1.f + __expf(-x)); }

// Target preprocessing: grid (B,3), 64 threads. One thread per target;
// ballot prefix-sum compacts valid targets in order (preserves last-wins scatter).
// Writes 4 inert pad entries so the loss loop can unroll by 4.
__global__ void k_tgt(const float* __restrict__ tg, int T,
                      int fs0, int fs1, int fs2)
{
    int b     = blockIdx.x;
    int layer = blockIdx.y;
    int tid   = threadIdx.x;
    if (b == 0 && layer == 0 && tid == 0) g_acc = 0.0;

    int fs = (layer == 0) ? fs0 : ((layer == 1) ? fs1 : fs2);
    int group = 2 - layer;
    float fsf = (float)fs;
    int base = (layer*16 + b);

    bool valid = false;
    float cf = 0.f, tx = 0.f, ty = 0.f, tw = 0.f, th = 0.f;
    if (tid < T) {
        const float* L = tg + ((size_t)b*T + tid)*5;
        cf = L[0];
        float x = L[1], y = L[2], w = L[3], h = L[4];
        valid = (cf + x + y + w + h) > 0.f;
        tx = x*fsf; ty = y*fsf; tw = w*fsf; th = h*fsf;
    }

    __shared__ int s_w0, s_total;
    int lane = tid & 31, wi = tid >> 5;
    unsigned ball = __ballot_sync(0xffffffffu, valid);
    int pre = __popc(ball & ((1u << lane) - 1u));
    if (wi == 0 && lane == 0) s_w0 = __popc(ball);
    __syncthreads();
    if (wi == 1) pre += s_w0;
    if (tid == 32) s_total = s_w0 + __popc(ball);
    __syncthreads();
    int total = s_total;
    if (tid == 0) g_cnt[base] = total;

    // 4 inert pad entries: never intersect, never match any cell key
    if (tid < 4) {
        int idx = base*TPAD + total + tid;
        g_box[idx]  = make_float4(2e9f, 2e9f, -2e9f, -2e9f);
        g_meta[idx] = make_float2(0.f, __int_as_float(-1));
    }

    if (!valid) return;

    float twth = tw*th;
    // argmax over 9 anchor IoUs (first max wins)
    float best = -1.f; int bi = 0;
    #pragma unroll
    for (int i = 0; i < 9; ++i) {
        float aw = c_allg[layer][2*i], ah = c_allg[layer][2*i+1];
        float mw = fminf(tw, aw), mh = fminf(th, ah);
        float inter = (mw > 0.f && mh > 0.f) ? mw*mh : 0.f;
        float iou = inter / (twth + aw*ah - inter);
        if (iou > best) { best = iou; bi = i; }
    }
    int bn = bi - (bi/3)*3;
    bool sel = (bi/3) == group;

    g_box[base*TPAD + pre] = make_float4(tx - 0.5f*tw, ty - 0.5f*th,
                                         tx + 0.5f*tw, ty + 0.5f*th);
    int key = -1;
    if (sel) {
        int gi = (int)tx, gj = (int)ty;
        if (gi >= 0 && gi < fs && gj >= 0 && gj < fs) {   // mode='drop'
            key = (bn << 28) | (gj << 14) | gi;
            float aw = c_allg[layer][2*(3*group + bn)];
            float ah = c_allg[layer][2*(3*group + bn) + 1];
            g_ext4[base*TMAX + pre] = make_float4(tx - (float)gi, ty - (float)gj,
                                      logf(tw/aw + 1e-16f), logf(th/ah + 1e-16f));
            g_ext2[base*TMAX + pre] = make_float2(sqrtf(2.f - twth/(fsf*fsf)),
                                      __int_as_float((int)cf));
        }
    }
    g_meta[base*TPAD + pre] = make_float2(0.7f*twth, __int_as_float(key));
}

// Per-cell loss. 128 threads/block, 1 cell/thread, target loop unrolled x4.
// 1D grid: bx = chunk*16 + batch (batch fastest -> round-robin balance).
__global__ __launch_bounds__(128)
void k_loss(const float* __restrict__ r0, const float* __restrict__ r1,
            const float* __restrict__ r2,
            int HW0, int W0, int HW1, int W1, int HW2, int W2,
            int nc0, int nc01, float* __restrict__ out)
{
    __shared__ float4 sbox[TPAD];
    __shared__ float2 smeta[TPAD];
    __shared__ float4 sext4[TMAX];
    __shared__ float2 sext2[TMAX];
    __shared__ int scnt;
    __shared__ float swsum[4];

    int bx    = blockIdx.x;
    int b     = bx & 15;
    int chunk = bx >> 4;

    int layer; const float* raw; int HW, W, base;
    if (chunk < nc0)       { layer = 0; raw = r0; HW = HW0; W = W0; base = 0;    }
    else if (chunk < nc01) { layer = 1; raw = r1; HW = HW1; W = W1; base = nc0;  }
    else                   { layer = 2; raw = r2; HW = HW2; W = W2; base = nc01; }

    int tid = threadIdx.x;
    int lb  = layer*16 + b;

    // ---- compute cell indices and ISSUE global loads first (overlap barrier) ----
    int cell = (chunk - base)*128 + tid;
    bool live = cell < 3*HW;
    int a = 0, h = 0, w = 0, hw = 0;
    float o0 = 0.f, o1 = 0.f, o2 = 0.f, o3 = 0.f, o4 = 0.f;
    const float* p = raw;
    if (live) {
        float invHW = 1.f/(float)HW, invW = 1.f/(float)W;
        a  = (int)((float)cell * invHW);
        hw = cell - a*HW;
        if (hw < 0)        { a--; hw += HW; }
        else if (hw >= HW) { a++; hw -= HW; }
        h = (int)((float)hw * invW);
        w = hw - h*W;
        if (w < 0)       { h--; w += W; }
        else if (w >= W) { h++; w -= W; }
        p = raw + ((size_t)b*255 + (size_t)a*85)*(size_t)HW + hw;
        o0 = __ldg(p);
        o1 = __ldg(p + HW);
        o2 = __ldg(p + 2*HW);
        o3 = __ldg(p + 3*HW);
        o4 = __ldg(p + 4*HW);
    }

    // ---- cooperative smem fill (loads above are in flight) ----
    if (tid < TPAD) { sbox[tid] = g_box[lb*TPAD + tid]; smeta[tid] = g_meta[lb*TPAD + tid]; }
    if (tid < TMAX) { sext4[tid] = g_ext4[lb*TMAX + tid]; sext2[tid] = g_ext2[lb*TMAX + tid]; }
    if (tid == 0) scnt = g_cnt[lb];
    __syncthreads();

    float lsum = 0.f;
    if (live) {
        float s0 = sigm(o0), s1 = sigm(o1), s4 = sigm(o4);
        float maw = c_allg[layer][2*(3*(2-layer) + a)];
        float mah = c_allg[layer][2*(3*(2-layer) + a) + 1];
        float pw = __expf(o2)*maw, ph = __expf(o3)*mah;
        float px = s0 + (float)w, py = s1 + (float)h;
        float atlx = px - 0.5f*pw, atly = py - 0.5f*ph;
        float abrx = px + 0.5f*pw, abry = py + 0.5f*ph;
        float ca = 0.7f*(pw*ph);
        int ckey = (a << 28) | (h << 14) | w;

        int any = 0;
        int tmi = -1;
        int cnt4 = (scnt + 3) & ~3;
        for (int t = 0; t < cnt4; t += 4) {
            float4 b0 = sbox[t],   b1 = sbox[t+1], b2 = sbox[t+2], b3 = sbox[t+3];
            float2 m0 = smeta[t],  m1 = smeta[t+1], m2 = smeta[t+2], m3 = smeta[t+3];
            // piou > 0.7  <=>  ix>0 & iy>0 & 1.7*ai - 0.7*areaA > 0.7*areaB
            {
                float ix = fminf(abrx, b0.z) - fmaxf(atlx, b0.x);
                float iy = fminf(abry, b0.w) - fmaxf(atly, b0.y);
                any |= (fminf(ix, iy) > 0.f) & (fmaf(1.7f, ix*iy, -ca) > m0.x);
                tmi = (__float_as_int(m0.y) == ckey) ? (t)   : tmi;
            }
            {
                float ix = fminf(abrx, b1.z) - fmaxf(atlx, b1.x);
                float iy = fminf(abry, b1.w) - fmaxf(atly, b1.y);
                any |= (fminf(ix, iy) > 0.f) & (fmaf(1.7f, ix*iy, -ca) > m1.x);
                tmi = (__float_as_int(m1.y) == ckey) ? (t+1) : tmi;
            }
            {
                float ix = fminf(abrx, b2.z) - fmaxf(atlx, b2.x);
                float iy = fminf(abry, b2.w) - fmaxf(atly, b2.y);
                any |= (fminf(ix, iy) > 0.f) & (fmaf(1.7f, ix*iy, -ca) > m2.x);
                tmi = (__float_as_int(m2.y) == ckey) ? (t+2) : tmi;
            }
            {
                float ix = fminf(abrx, b3.z) - fmaxf(atlx, b3.x);
                float iy = fminf(abry, b3.w) - fmaxf(atly, b3.y);
                any |= (fminf(ix, iy) > 0.f) & (fmaf(1.7f, ix*iy, -ca) > m3.x);
                tmi = (__float_as_int(m3.y) == ckey) ? (t+3) : tmi;
            }
        }

        if (tmi >= 0) {
            float4 e4 = sext4[tmi];
            float2 e2 = sext2[tmi];
            float ts2 = e2.x*e2.x;
            int cls = __float_as_int(e2.y);
            // BCE(xy) weighted by scale^2
            lsum -= ts2*( e4.x*slog(s0) + (1.f - e4.x)*slog(1.f - s0)
                        + e4.y*slog(s1) + (1.f - e4.y)*slog(1.f - s1) );
            // 0.5 * scale^2 * (wh diff)^2
            float dw = o2 - e4.z, dh = o3 - e4.w;
            lsum += 0.5f*ts2*(dw*dw + dh*dh);
            // obj BCE, target 1
            lsum -= slog(s4);
            // class BCE over 80 channels (rare path)
            for (int c = 0; c < 80; ++c) {
                float scc = sigm(__ldg(p + (size_t)(5 + c)*HW));
                lsum -= (c == cls) ? slog(scc) : slog(1.f - scc);
            }
        } else if (!any) {
            // obj BCE, target 0 where obj_mask = 1
            lsum -= slog(1.f - s4);
        }
        // (any && tmi<0) -> obj_mask = 0 -> zero contribution
    }

    // block reduction + one atomic per block; globally-last block writes output
    #pragma unroll
    for (int off = 16; off; off >>= 1)
        lsum += __shfl_xor_sync(0xffffffffu, lsum, off);
    if ((tid & 31) == 0) swsum[tid >> 5] = lsum;
    __syncthreads();
    if (tid == 0) {
        double bsum = (double)swsum[0] + (double)swsum[1]
                    + (double)swsum[2] + (double)swsum[3];
        atomicAdd(&g_acc, bsum);
        __threadfence();
        unsigned prev = atomicAdd(&g_count, 1u);
        if (prev == gridDim.x - 1u) {
            out[0] = (float)g_acc;
            g_acc = 0.0;       // reset for next graph replay
            g_count = 0u;
        }
    }
}

extern "C" void kernel_launch(void* const* d_in, const int* in_sizes, int n_in,
                              void* d_out, int out_size)
{
    const float* r0 = (const float*)d_in[0];
    const float* r1 = (const float*)d_in[1];
    const float* r2 = (const float*)d_in[2];
    const float* targets = (const float*)d_in[3];
    const int B = 16;
    int T = in_sizes[3] / (B*5);
    if (T > TMAX) T = TMAX;

    int HW0 = in_sizes[0] / (B*255);
    int HW1 = in_sizes[1] / (B*255);
    int HW2 = in_sizes[2] / (B*255);
    int W0 = (int)(sqrt((double)HW0) + 0.5);
    int W1 = (int)(sqrt((double)HW1) + 0.5);
    int W2 = (int)(sqrt((double)HW2) + 0.5);

    dim3 tgrid(B, 3);
    k_tgt<<<tgrid, 64>>>(targets, T, W0, W1, W2);

    int nc0 = (3*HW0 + 127)/128;
    int nc1 = (3*HW1 + 127)/128;
    int nc2 = (3*HW2 + 127)/128;
    int nblocks = (nc0 + nc1 + nc2) * 16;
    k_loss<<<nblocks, 128>>>(r0, r1, r2,
                             HW0, W0, HW1, W1, HW2, W2,
                             nc0, nc0 + nc1, (float*)d_out);
}

// round 7
// speedup vs baseline: 2.2691x; 1.0051x over previous
#include <cuda_runtime.h>
#include <math.h>

#define TMAX 64
#define TPAD 68   // TMAX + 4 pad slots for the x4-unrolled loops

// ANCHORS/stride per layer (exact: divisors are powers of two, bit-identical to fdiv)
__constant__ float c_allg[3][18] = {
  {0.3125f,0.40625f, 0.5f,0.9375f, 1.03125f,0.71875f, 0.9375f,1.90625f, 1.9375f,1.40625f,
   1.84375f,3.71875f, 3.625f,2.8125f, 4.875f,6.1875f, 11.65625f,10.1875f},
  {0.625f,0.8125f, 1.0f,1.875f, 2.0625f,1.4375f, 1.875f,3.8125f, 3.875f,2.8125f,
   3.6875f,7.4375f, 7.25f,5.625f, 9.75f,12.375f, 23.3125f,20.375f},
  {1.25f,1.625f, 2.0f,3.75f, 4.125f,2.875f, 3.75f,7.625f, 7.75f,5.625f,
   7.375f,14.875f, 14.5f,11.25f, 19.5f,24.75f, 46.625f,40.75f}
};

__device__ double   g_acc   = 0.0;
__device__ unsigned g_count = 0u;

__device__ __forceinline__ float slog(float x) { return x > 0.f ? __logf(x) : -100.f; }
__device__ __forceinline__ float sigm(float x) { return 1.f/(1.f + __expf(-x)); }

// Single fused kernel. 128 threads/block, 1 cell/thread.
// 1D grid: bx = chunk*16 + batch (batch fastest -> round-robin balance).
// Threads 0-63 redundantly preprocess this (layer,batch)'s targets into smem
// (cheap: constant anchor table, no divisions), overlapped with the in-flight
// main LDGs. Ignore-test loop and assigned-key loop are split; key list is
// compacted (only selected+in-bounds targets).
__global__ __launch_bounds__(128)
void k_loss(const float* __restrict__ r0, const float* __restrict__ r1,
            const float* __restrict__ r2, const float* __restrict__ tg,
            int T,
            int HW0, int W0, int HW1, int W1, int HW2, int W2,
            int nc0, int nc01, float* __restrict__ out)
{
    __shared__ float4 sbox[TPAD];    // target tl.x, tl.y, br.x, br.y
    __shared__ float  sarea[TPAD];   // 0.7 * target area
    __shared__ int    skey[TPAD];    // compacted assigned-cell keys
    __shared__ float4 sext4[TMAX];   // fx, fy, log(w/aw), log(h/ah)  (key-indexed)
    __shared__ float2 sext2[TMAX];   // scale, cls                     (key-indexed)
    __shared__ int    s_cnt2[2], s_kc2[2];
    __shared__ int    scnt, skcnt;
    __shared__ float  swsum[4];

    int bx    = blockIdx.x;
    int b     = bx & 15;
    int chunk = bx >> 4;

    int layer; const float* raw; int HW, W, base;
    if (chunk < nc0)       { layer = 0; raw = r0; HW = HW0; W = W0; base = 0;    }
    else if (chunk < nc01) { layer = 1; raw = r1; HW = HW1; W = W1; base = nc0;  }
    else                   { layer = 2; raw = r2; HW = HW2; W = W2; base = nc01; }

    int tid = threadIdx.x;
    int fs  = W;
    float fsf = (float)fs;
    int group = 2 - layer;

    // ---- compute cell indices and ISSUE main global loads first ----
    int cell = (chunk - base)*128 + tid;
    bool live = cell < 3*HW;
    int a = 0, h = 0, w = 0;
    float o0 = 0.f, o1 = 0.f, o2 = 0.f, o3 = 0.f, o4 = 0.f;
    const float* p = raw;
    if (live) {
        float invHW = 1.f/(float)HW, invW = 1.f/(float)W;
        a = (int)((float)cell * invHW);
        int hw = cell - a*HW;
        if (hw < 0)        { a--; hw += HW; }
        else if (hw >= HW) { a++; hw -= HW; }
        h = (int)((float)hw * invW);
        w = hw - h*W;
        if (w < 0)       { h--; w += W; }
        else if (w >= W) { h++; w -= W; }
        p = raw + ((size_t)b*255 + (size_t)a*85)*(size_t)HW + hw;
        o0 = __ldg(p);
        o1 = __ldg(p + HW);
        o2 = __ldg(p + 2*HW);
        o3 = __ldg(p + 3*HW);
        o4 = __ldg(p + 4*HW);
    }

    // ---- phase 1: target preprocessing (threads 0..63, two warps) ----
    bool valid = false;
    float cf = 0.f, tx = 0.f, ty = 0.f, tw = 0.f, th = 0.f;
    unsigned ball = 0; int pre = 0;
    if (tid < 64) {
        if (tid < T) {
            const float* L = tg + ((size_t)b*T + tid)*5;
            cf = L[0];
            float x = L[1], y = L[2], ww = L[3], hh = L[4];
            valid = (cf + x + y + ww + hh) > 0.f;
            tx = x*fsf; ty = y*fsf; tw = ww*fsf; th = hh*fsf;
        }
        ball = __ballot_sync(0xffffffffu, valid);
        pre = __popc(ball & ((1u << (tid & 31)) - 1u));
        if ((tid & 31) == 0) s_cnt2[tid >> 5] = __popc(ball);
    }
    __syncthreads();

    int key = -1; int bn = 0, gi = 0, gj = 0; float twth = 0.f;
    unsigned kb = 0; int kpre = 0;
    if (tid < 64) {
        if (tid >= 32) pre += s_cnt2[0];
        int total = s_cnt2[0] + s_cnt2[1];
        if (valid) {
            twth = tw*th;
            // argmax over 9 anchor IoUs (first max wins)
            float best = -1.f; int bi = 0;
            #pragma unroll
            for (int i = 0; i < 9; ++i) {
                float aw = c_allg[layer][2*i], ah = c_allg[layer][2*i+1];
                float mw = fminf(tw, aw), mh = fminf(th, ah);
                float inter = (mw > 0.f && mh > 0.f) ? mw*mh : 0.f;
                float iou = inter / (twth + aw*ah - inter);
                if (iou > best) { best = iou; bi = i; }
            }
            bn = bi - (bi/3)*3;
            sbox[pre]  = make_float4(tx - 0.5f*tw, ty - 0.5f*th,
                                     tx + 0.5f*tw, ty + 0.5f*th);
            sarea[pre] = 0.7f*twth;
            if ((bi/3) == group) {
                gi = (int)tx; gj = (int)ty;
                if (gi >= 0 && gi < fs && gj >= 0 && gj < fs)   // mode='drop'
                    key = (bn << 28) | (gj << 14) | gi;
            }
        }
        kb = __ballot_sync(0xffffffffu, key >= 0);
        kpre = __popc(kb & ((1u << (tid & 31)) - 1u));
        if ((tid & 31) == 0) s_kc2[tid >> 5] = __popc(kb);
        // inert box pads (threads 32..35 know total)
        if (tid >= 32 && tid < 36) {
            int i = total + (tid - 32);
            sbox[i]  = make_float4(2e9f, 2e9f, -2e9f, -2e9f);
            sarea[i] = 0.f;
        }
        if (tid == 0) scnt = total;
    }
    __syncthreads();

    if (tid < 64) {
        if (tid >= 32) kpre += s_kc2[0];
        int ktotal = s_kc2[0] + s_kc2[1];
        if (key >= 0) {
            skey[kpre] = key;
            float aw = c_allg[layer][2*(3*group + bn)];
            float ah = c_allg[layer][2*(3*group + bn) + 1];
            sext4[kpre] = make_float4(tx - (float)gi, ty - (float)gj,
                                      logf(tw/aw + 1e-16f), logf(th/ah + 1e-16f));
            sext2[kpre] = make_float2(sqrtf(2.f - twth/(fsf*fsf)),
                                      __int_as_float((int)cf));
        }
        if (tid >= 32 && tid < 36) skey[ktotal + (tid - 32)] = -1;  // key pads
        if (tid == 0) skcnt = ktotal;
    }
    __syncthreads();

    // ---- phase 2: per-cell loss ----
    float lsum = 0.f;
    if (live) {
        float s0 = sigm(o0), s1 = sigm(o1), s4 = sigm(o4);
        float maw = c_allg[layer][2*(3*group + a)];
        float mah = c_allg[layer][2*(3*group + a) + 1];
        float pw = __expf(o2)*maw, ph = __expf(o3)*mah;
        float px = s0 + (float)w, py = s1 + (float)h;
        float atlx = px - 0.5f*pw, atly = py - 0.5f*ph;
        float abrx = px + 0.5f*pw, abry = py + 0.5f*ph;
        float ca = 0.7f*(pw*ph);
        int ckey = (a << 28) | (h << 14) | w;

        // ignore test: piou > 0.7  <=>  ix>0 & iy>0 & 1.7*ai - 0.7*(A+B) > 0
        float anyf = -1e30f;
        int cnt4 = (scnt + 3) & ~3;
        for (int t = 0; t < cnt4; t += 4) {
            float4 b0 = sbox[t],  b1 = sbox[t+1], b2 = sbox[t+2], b3 = sbox[t+3];
            float a0 = sarea[t],  a1 = sarea[t+1], a2 = sarea[t+2], a3 = sarea[t+3];
            {
                float ix = fminf(abrx, b0.z) - fmaxf(atlx, b0.x);
                float iy = fminf(abry, b0.w) - fmaxf(atly, b0.y);
                float lhs = fmaf(1.7f, ix*iy, -ca) - a0;
                anyf = fmaxf(anyf, fminf(fminf(ix, iy), lhs));
            }
            {
                float ix = fminf(abrx, b1.z) - fmaxf(atlx, b1.x);
                float iy = fminf(abry, b1.w) - fmaxf(atly, b1.y);
                float lhs = fmaf(1.7f, ix*iy, -ca) - a1;
                anyf = fmaxf(anyf, fminf(fminf(ix, iy), lhs));
            }
            {
                float ix = fminf(abrx, b2.z) - fmaxf(atlx, b2.x);
                float iy = fminf(abry, b2.w) - fmaxf(atly, b2.y);
                float lhs = fmaf(1.7f, ix*iy, -ca) - a2;
                anyf = fmaxf(anyf, fminf(fminf(ix, iy), lhs));
            }
            {
                float ix = fminf(abrx, b3.z) - fmaxf(atlx, b3.x);
                float iy = fminf(abry, b3.w) - fmaxf(atly, b3.y);
                float lhs = fmaf(1.7f, ix*iy, -ca) - a3;
                anyf = fmaxf(anyf, fminf(fminf(ix, iy), lhs));
            }
        }

        // assigned-cell match over compacted key list (last match wins)
        int tmi = -1;
        int kcnt4 = (skcnt + 3) & ~3;
        for (int t = 0; t < kcnt4; t += 4) {
            int k0 = skey[t], k1 = skey[t+1], k2 = skey[t+2], k3 = skey[t+3];
            tmi = (k0 == ckey) ? t   : tmi;
            tmi = (k1 == ckey) ? t+1 : tmi;
            tmi = (k2 == ckey) ? t+2 : tmi;
            tmi = (k3 == ckey) ? t+3 : tmi;
        }

        if (tmi >= 0) {
            float4 e4 = sext4[tmi];
            float2 e2 = sext2[tmi];
            float ts2 = e2.x*e2.x;
            int cls = __float_as_int(e2.y);
            // BCE(xy) weighted by scale^2
            lsum -= ts2*( e4.x*slog(s0) + (1.f - e4.x)*slog(1.f - s0)
                        + e4.y*slog(s1) + (1.f - e4.y)*slog(1.f - s1) );
            // 0.5 * scale^2 * (wh diff)^2
            float dw = o2 - e4.z, dh = o3 - e4.w;
            lsum += 0.5f*ts2*(dw*dw + dh*dh);
            // obj BCE, target 1 (obj_mask forced to 1 at assigned cells)
            lsum -= slog(s4);
            // class BCE over 80 channels (rare path)
            for (int c = 0; c < 80; ++c) {
                float scc = sigm(__ldg(p + (size_t)(5 + c)*HW));
                lsum -= (c == cls) ? slog(scc) : slog(1.f - scc);
            }
        } else if (!(anyf > 0.f)) {
            // obj BCE, target 0 where obj_mask = 1
            lsum -= slog(1.f - s4);
        }
        // (ignored && not assigned) -> obj_mask = 0 -> zero contribution
    }

    // ---- phase 3: block reduction + one atomic; globally-last block writes ----
    #pragma unroll
    for (int off = 16; off; off >>= 1)
        lsum += __shfl_xor_sync(0xffffffffu, lsum, off);
    if ((tid & 31) == 0) swsum[tid >> 5] = lsum;
    __syncthreads();
    if (tid == 0) {
        double bsum = (double)swsum[0] + (double)swsum[1]
                    + (double)swsum[2] + (double)swsum[3];
        atomicAdd(&g_acc, bsum);
        __threadfence();
        unsigned prev = atomicAdd(&g_count, 1u);
        if (prev == gridDim.x - 1u) {
            out[0] = (float)g_acc;
            g_acc = 0.0;       // reset for next graph replay
            g_count = 0u;
        }
    }
}

extern "C" void kernel_launch(void* const* d_in, const int* in_sizes, int n_in,
                              void* d_out, int out_size)
{
    const float* r0 = (const float*)d_in[0];
    const float* r1 = (const float*)d_in[1];
    const float* r2 = (const float*)d_in[2];
    const float* targets = (const float*)d_in[3];
    const int B = 16;
    int T = in_sizes[3] / (B*5);
    if (T > TMAX) T = TMAX;

    int HW0 = in_sizes[0] / (B*255);
    int HW1 = in_sizes[1] / (B*255);
    int HW2 = in_sizes[2] / (B*255);
    int W0 = (int)(sqrt((double)HW0) + 0.5);
    int W1 = (int)(sqrt((double)HW1) + 0.5);
    int W2 = (int)(sqrt((double)HW2) + 0.5);

    int nc0 = (3*HW0 + 127)/128;
    int nc1 = (3*HW1 + 127)/128;
    int nc2 = (3*HW2 + 127)/128;
    int nblocks = (nc0 + nc1 + nc2) * 16;
    k_loss<<<nblocks, 128>>>(r0, r1, r2, targets, T,
                             HW0, W0, HW1, W1, HW2, W2,
                             nc0, nc0 + nc1, (float*)d_out);
}